// round 10
// baseline (speedup 1.0000x reference)
#include <cuda_runtime.h>

#define T_STEPS 16384
#define X_DIM   512
#define H_DIM   1024
#define NBLK    128
#define ROWS_PER_BLK 8                 // rows per block, 1 warp per row
#define NTHREADS 256
#define SHARDS  8                      // mailbox copies; 16 blocks poll each shard
#define QWORDS  (H_DIM / NTHREADS)     // gather words per thread == 4 (MUST track NTHREADS)

// Tagged mailbox shards: word = (tag<<32)|fp32, tag = t+1 (0 == empty).
// Double-buffered by step parity; buffer reuse is gated by the gather-before-
// next-push dependency. Cross-replay stale tags can only match the same step
// index -> identical (deterministic) value, so no reset is needed.
__device__ unsigned long long g_mbox[2][SHARDS][H_DIM];

__device__ __forceinline__ unsigned long long ld_relaxed_u64(const unsigned long long* p) {
    unsigned long long v;
    asm volatile("ld.relaxed.gpu.global.u64 %0, [%1];" : "=l"(v) : "l"(p) : "memory");
    return v;
}
__device__ __forceinline__ void st_relaxed_u64(unsigned long long* p, unsigned long long v) {
    asm volatile("st.relaxed.gpu.global.u64 [%0], %1;" :: "l"(p), "l"(v) : "memory");
}
__device__ __forceinline__ void prefetch_l2(const void* p) {
    asm volatile("prefetch.global.L2 [%0];" :: "l"(p));
}
// MUFU.TANH, ~16cyc. Contracting recurrence keeps the approx error bounded
// (R6: rel_err 5e-6).
__device__ __forceinline__ float tanh_fast(float x) {
    float y;
    asm volatile("tanh.approx.f32 %0, %1;" : "=f"(y) : "f"(x));
    return y;
}

__global__ void __launch_bounds__(NTHREADS, 1)
rnn_scan_kernel(const float* __restrict__ x_seq,
                const float* __restrict__ h0,
                const float* __restrict__ A_raw,
                const float* __restrict__ B,
                const float* __restrict__ c,
                float* __restrict__ out)
{
    const int warp = threadIdx.x >> 5;
    const int lane = threadIdx.x & 31;
    const int row  = blockIdx.x * ROWS_PER_BLK + warp;

    __shared__ float4 Bs4[ROWS_PER_BLK][X_DIM / 4];   // 16 KB
    __shared__ float  h_sm[2][H_DIM];                 // 8 KB double buffer

    // ---- Prologue: A = 0.9 I + 0.1 A_raw, row in float4 registers.
    const float4* Ar = (const float4*)(A_raw + (size_t)row * H_DIM);
    float4 a4[8];
#pragma unroll
    for (int k = 0; k < 8; ++k) {
        float4 v = Ar[lane + 32 * k];
        int j = 4 * (lane + 32 * k);
        v.x *= 0.1f; v.y *= 0.1f; v.z *= 0.1f; v.w *= 0.1f;
        if (j + 0 == row) v.x += 0.9f;
        if (j + 1 == row) v.y += 0.9f;
        if (j + 2 == row) v.z += 0.9f;
        if (j + 3 == row) v.w += 0.9f;
        a4[k] = v;
    }
    {
        const float4* Bg = (const float4*)(B + (size_t)blockIdx.x * ROWS_PER_BLK * X_DIM);
        for (int i = threadIdx.x; i < ROWS_PER_BLK * (X_DIM / 4); i += NTHREADS)
            Bs4[i / (X_DIM / 4)][i % (X_DIM / 4)] = Bg[i];
    }
    const float c_r = (lane == 0) ? c[row] : 0.0f;

    for (int i = threadIdx.x; i < H_DIM; i += NTHREADS)
        h_sm[0][i] = h0[i];

    // Deep x pipeline: x0 consumed now for bx(0); xn holds x[t+1], always
    // loaded one FULL step before its bx is computed (no exposed stall).
    float4 xn[4];
    float bxp;
    {
        const float4* xt0 = (const float4*)x_seq;
        float4 x0[4];
#pragma unroll
        for (int k = 0; k < 4; ++k) x0[k] = xt0[lane + 32 * k];
        const float4* xt1 = (const float4*)(x_seq + X_DIM);
#pragma unroll
        for (int k = 0; k < 4; ++k) xn[k] = xt1[lane + 32 * k];
        if (threadIdx.x < 16) prefetch_l2(x_seq + 2 * X_DIM + threadIdx.x * 32);
        __syncthreads();
        float s0 = 0.f, s1 = 0.f;
#pragma unroll
        for (int k = 0; k < 4; ++k) {
            float4 b = Bs4[warp][lane + 32 * k];
            s0 += b.x * x0[k].x + b.z * x0[k].z;
            s1 += b.y * x0[k].y + b.w * x0[k].w;
        }
        bxp = s0 + s1;
    }

    const int shard = blockIdx.x >> 4;   // 16 blocks per shard

    for (int t = 0; t < T_STEPS; ++t) {
        const int cur = t & 1;

        // ---- 1) A . h_t (float4 LDS, conflict-free) + bx partial.
        const float4* hp = (const float4*)h_sm[cur];
        float4 h4[8];
#pragma unroll
        for (int k = 0; k < 8; ++k) h4[k] = hp[lane + 32 * k];
        float s0 = bxp + c_r, s1 = 0.f, s2 = 0.f, s3 = 0.f;
#pragma unroll
        for (int k = 0; k < 8; ++k) {
            s0 += a4[k].x * h4[k].x;
            s1 += a4[k].y * h4[k].y;
            s2 += a4[k].z * h4[k].z;
            s3 += a4[k].w * h4[k].w;
        }
        float acc = (s0 + s1) + (s2 + s3);

        // ---- 2) Butterfly reduce (redux.f32 doesn't exist on sm_103).
#pragma unroll
        for (int off = 16; off; off >>= 1)
            acc += __shfl_xor_sync(0xffffffffu, acc, off);

        float hval = tanh_fast(acc);

        // ---- 3) Push FIRST (critical path); out-store on a non-push lane.
        {
            unsigned long long w =
                ((unsigned long long)(unsigned)(t + 1) << 32) | __float_as_uint(hval);
            if (lane < SHARDS)
                st_relaxed_u64(&g_mbox[cur][lane][row], w);
        }
        if (lane == 8)
            out[(size_t)t * H_DIM + row] = hval;

        if (t + 1 < T_STEPS) {
            // ---- 4) Issue probes immediately after push (full H coverage:
            // QWORDS * NTHREADS == H_DIM).
            const unsigned want = (unsigned)(t + 1);
            unsigned long long* slot = &g_mbox[cur][shard][0];
            unsigned long long q[QWORDS];
#pragma unroll
            for (int k = 0; k < QWORDS; ++k)
                q[k] = ld_relaxed_u64(&slot[threadIdx.x + NTHREADS * k]);

            // ---- 5) bx for t+1 from xn loaded a FULL step ago: zero stall.
            float b0 = 0.f, b1 = 0.f;
#pragma unroll
            for (int k = 0; k < 4; ++k) {
                float4 b = Bs4[warp][lane + 32 * k];
                b0 += b.x * xn[k].x + b.z * xn[k].z;
                b1 += b.y * xn[k].y + b.w * xn[k].w;
            }
            bxp = b0 + b1;

            // ---- 6) Refill xn with x[t+2]; it has a whole step to land.
            if (t + 2 < T_STEPS) {
                const float4* xt2 = (const float4*)(x_seq + (size_t)(t + 2) * X_DIM);
#pragma unroll
                for (int k = 0; k < 4; ++k) xn[k] = xt2[lane + 32 * k];
                if (t + 3 < T_STEPS && threadIdx.x < 16)
                    prefetch_l2(x_seq + (size_t)(t + 3) * X_DIM + threadIdx.x * 32);
            }

            // ---- 7) Check probes (landed during bx); retry misses.
            for (;;) {
                bool miss = false;
#pragma unroll
                for (int k = 0; k < QWORDS; ++k) {
                    if ((unsigned)(q[k] >> 32) != want) {
                        q[k] = ld_relaxed_u64(&slot[threadIdx.x + NTHREADS * k]);
                        if ((unsigned)(q[k] >> 32) != want) miss = true;
                    }
                }
                if (!miss) break;
            }
#pragma unroll
            for (int k = 0; k < QWORDS; ++k)
                h_sm[cur ^ 1][threadIdx.x + NTHREADS * k] = __uint_as_float((unsigned)q[k]);
            __syncthreads();
        }
    }
}

extern "C" void kernel_launch(void* const* d_in, const int* in_sizes, int n_in,
                              void* d_out, int out_size)
{
    const float* x_seq = (const float*)d_in[0];
    const float* h0    = (const float*)d_in[1];
    const float* A_raw = (const float*)d_in[2];
    const float* B     = (const float*)d_in[3];
    const float* c     = (const float*)d_in[4];
    float* out = (float*)d_out;

    rnn_scan_kernel<<<NBLK, NTHREADS>>>(x_seq, h0, A_raw, B, c, out);
}

// round 11
// speedup vs baseline: 1.1337x; 1.1337x over previous
#include <cuda_runtime.h>

#define T_STEPS 16384
#define X_DIM   512
#define H_DIM   1024
#define NBLK    128
#define ROWS_PER_BLK 8                 // rows per block, 1 warp per row
#define NTHREADS 256
#define SHARDS  8                      // mailbox copies; 16 blocks poll each shard
#define QWORDS  (H_DIM / NTHREADS)     // gather words per thread (tracks NTHREADS!)

typedef unsigned long long u64;

// Tagged mailbox shards: word = (tag<<32)|fp32, tag = t+1 (0 == empty).
// Double-buffered by step parity; buffer reuse is gated by the gather-before-
// next-push dependency. Cross-replay stale tags can only match the same step
// index -> identical (deterministic) value, so no reset is needed.
__device__ u64 g_mbox[2][SHARDS][H_DIM];

__device__ __forceinline__ u64 ld_relaxed_u64(const u64* p) {
    u64 v;
    asm volatile("ld.relaxed.gpu.global.u64 %0, [%1];" : "=l"(v) : "l"(p) : "memory");
    return v;
}
__device__ __forceinline__ void st_relaxed_u64(u64* p, u64 v) {
    asm volatile("st.relaxed.gpu.global.u64 [%0], %1;" :: "l"(p), "l"(v) : "memory");
}
__device__ __forceinline__ void prefetch_l2(const void* p) {
    asm volatile("prefetch.global.L2 [%0];" :: "l"(p));
}
// MUFU.TANH, ~16cyc; contracting recurrence bounds the approx error (R6: 5e-6).
__device__ __forceinline__ float tanh_fast(float x) {
    float y;
    asm volatile("tanh.approx.f32 %0, %1;" : "=f"(y) : "f"(x));
    return y;
}
// Packed f32x2 ops (sm_100+; PTX-only — ptxas never auto-fuses these).
__device__ __forceinline__ u64 pack2(float lo, float hi) {
    u64 r; asm("mov.b64 %0, {%1, %2};" : "=l"(r) : "f"(lo), "f"(hi)); return r;
}
__device__ __forceinline__ void unpack2(u64 v, float& lo, float& hi) {
    asm("mov.b64 {%0, %1}, %2;" : "=f"(lo), "=f"(hi) : "l"(v));
}
__device__ __forceinline__ u64 ffma2(u64 a, u64 b, u64 c) {
    u64 d; asm("fma.rn.f32x2 %0, %1, %2, %3;" : "=l"(d) : "l"(a), "l"(b), "l"(c)); return d;
}
__device__ __forceinline__ u64 fadd2(u64 a, u64 b) {
    u64 d; asm("add.rn.f32x2 %0, %1, %2;" : "=l"(d) : "l"(a), "l"(b)); return d;
}

__global__ void __launch_bounds__(NTHREADS, 1)
rnn_scan_kernel(const float* __restrict__ x_seq,
                const float* __restrict__ h0,
                const float* __restrict__ A_raw,
                const float* __restrict__ B,
                const float* __restrict__ c,
                float* __restrict__ out)
{
    const int warp = threadIdx.x >> 5;
    const int lane = threadIdx.x & 31;
    const int row  = blockIdx.x * ROWS_PER_BLK + warp;

    __shared__ float4 Bs4[ROWS_PER_BLK][X_DIM / 4];   // 16 KB
    __shared__ float  h_sm[2][H_DIM];                 // 8 KB double buffer

    // ---- Prologue: A = 0.9 I + 0.1 A_raw, row packed into 16 u64 (f32x2).
    const float4* Ar = (const float4*)(A_raw + (size_t)row * H_DIM);
    u64 ap[16];
#pragma unroll
    for (int k = 0; k < 8; ++k) {
        float4 v = Ar[lane + 32 * k];
        int j = 4 * (lane + 32 * k);
        v.x *= 0.1f; v.y *= 0.1f; v.z *= 0.1f; v.w *= 0.1f;
        if (j + 0 == row) v.x += 0.9f;
        if (j + 1 == row) v.y += 0.9f;
        if (j + 2 == row) v.z += 0.9f;
        if (j + 3 == row) v.w += 0.9f;
        ap[2 * k]     = pack2(v.x, v.y);
        ap[2 * k + 1] = pack2(v.z, v.w);
    }
    {
        const float4* Bg = (const float4*)(B + (size_t)blockIdx.x * ROWS_PER_BLK * X_DIM);
        for (int i = threadIdx.x; i < ROWS_PER_BLK * (X_DIM / 4); i += NTHREADS)
            Bs4[i / (X_DIM / 4)][i % (X_DIM / 4)] = Bg[i];
    }
    const float c_r = (lane == 0) ? c[row] : 0.0f;

    for (int i = threadIdx.x; i < H_DIM; i += NTHREADS)
        h_sm[0][i] = h0[i];

    // x for step 0 into registers (as packed u64 pairs).
    ulonglong2 xn[4];
    {
        const ulonglong2* xt = (const ulonglong2*)x_seq;
#pragma unroll
        for (int k = 0; k < 4; ++k) xn[k] = xt[lane + 32 * k];
        if (threadIdx.x < 16) prefetch_l2(x_seq + X_DIM + threadIdx.x * 32);
    }
    __syncthreads();

    const ulonglong2* bp2 = (const ulonglong2*)&Bs4[warp][0];

    // bx partial for step 0 (packed FMA).
    float bxp;
    {
        u64 b0 = 0ull, b1 = 0ull;
#pragma unroll
        for (int k = 0; k < 4; ++k) {
            ulonglong2 bq = bp2[lane + 32 * k];
            b0 = ffma2(bq.x, xn[k].x, b0);
            b1 = ffma2(bq.y, xn[k].y, b1);
        }
        float lo, hi;
        unpack2(fadd2(b0, b1), lo, hi);
        bxp = lo + hi;
    }

    const int shard = blockIdx.x >> 4;   // 16 blocks per shard

    for (int t = 0; t < T_STEPS; ++t) {
        const int cur = t & 1;

        // ---- 1) A . h_t with packed f32x2 FMA (16 FMA2 instead of 32 FFMA).
        const ulonglong2* hp2 = (const ulonglong2*)h_sm[cur];
        u64 acc0 = pack2(bxp + c_r, 0.0f);
        u64 acc1 = 0ull;
#pragma unroll
        for (int k = 0; k < 8; ++k) {
            ulonglong2 hq = hp2[lane + 32 * k];
            acc0 = ffma2(ap[2 * k],     hq.x, acc0);
            acc1 = ffma2(ap[2 * k + 1], hq.y, acc1);
        }
        float lo, hi;
        unpack2(fadd2(acc0, acc1), lo, hi);
        float acc = lo + hi;

        // ---- 2) Butterfly reduce (redux.f32 doesn't exist on sm_103).
#pragma unroll
        for (int off = 16; off; off >>= 1)
            acc += __shfl_xor_sync(0xffffffffu, acc, off);

        float hval = tanh_fast(acc);

        // ---- 3) Push FIRST (critical path); out-store on a non-push lane.
        {
            u64 w = ((u64)(unsigned)(t + 1) << 32) | __float_as_uint(hval);
            if (lane < SHARDS)
                st_relaxed_u64(&g_mbox[cur][lane][row], w);
        }
        if (lane == 8)
            out[(size_t)t * H_DIM + row] = hval;

        if (t + 1 < T_STEPS) {
            // ---- 4) Probes FIRST (reach L2 earliest), then x_{t+1} loads.
            // The bx consume-stall below spaces probe-issue from probe-check
            // by ~1 L2 RTT — this timing structure is load-bearing (R10).
            const unsigned want = (unsigned)(t + 1);
            u64* slot = &g_mbox[cur][shard][0];
            u64 q[QWORDS];
#pragma unroll
            for (int k = 0; k < QWORDS; ++k)
                q[k] = ld_relaxed_u64(&slot[threadIdx.x + NTHREADS * k]);

            const ulonglong2* xt1 = (const ulonglong2*)(x_seq + (size_t)(t + 1) * X_DIM);
#pragma unroll
            for (int k = 0; k < 4; ++k) xn[k] = xt1[lane + 32 * k];

            if (t + 2 < T_STEPS && threadIdx.x < 16)
                prefetch_l2(x_seq + (size_t)(t + 2) * X_DIM + threadIdx.x * 32);

            // bx for t+1: stalls on xn — the useful filler.
            u64 b0 = 0ull, b1 = 0ull;
#pragma unroll
            for (int k = 0; k < 4; ++k) {
                ulonglong2 bq = bp2[lane + 32 * k];
                b0 = ffma2(bq.x, xn[k].x, b0);
                b1 = ffma2(bq.y, xn[k].y, b1);
            }
            float blo, bhi;
            unpack2(fadd2(b0, b1), blo, bhi);
            bxp = blo + bhi;

            // ---- 5) Check probes (landed during bx); retry misses.
            for (;;) {
                bool miss = false;
#pragma unroll
                for (int k = 0; k < QWORDS; ++k) {
                    if ((unsigned)(q[k] >> 32) != want) {
                        q[k] = ld_relaxed_u64(&slot[threadIdx.x + NTHREADS * k]);
                        if ((unsigned)(q[k] >> 32) != want) miss = true;
                    }
                }
                if (!miss) break;
            }
#pragma unroll
            for (int k = 0; k < QWORDS; ++k)
                h_sm[cur ^ 1][threadIdx.x + NTHREADS * k] = __uint_as_float((unsigned)q[k]);
            __syncthreads();
        }
    }
}

extern "C" void kernel_launch(void* const* d_in, const int* in_sizes, int n_in,
                              void* d_out, int out_size)
{
    const float* x_seq = (const float*)d_in[0];
    const float* h0    = (const float*)d_in[1];
    const float* A_raw = (const float*)d_in[2];
    const float* B     = (const float*)d_in[3];
    const float* c     = (const float*)d_in[4];
    float* out = (float*)d_out;

    rnn_scan_kernel<<<NBLK, NTHREADS>>>(x_seq, h0, A_raw, B, c, out);
}